// round 3
// baseline (speedup 1.0000x reference)
#include <cuda_runtime.h>

#define NN 50000
#define NE 800000
#define D1 128
#define MID1 256
#define HIDC 200
#define MID2 400
#define OUTC 2
#define MSG_EPS 1e-7f
#define BN_EPS 1e-5f
#define CEIL(a, b) (((a) + (b) - 1) / (b))

// ---------------- device scratch (static globals; no allocations) ----------------
__device__ int g_deg[NN];
__device__ int g_rowstart[NN];
__device__ int g_cursor[NN];
__device__ int g_srcs[NE];
__device__ int g_blocksum[128];
__device__ int g_blockoff[128];

__device__ float g_t[(size_t)NN * 200];    // agg + residual (GEMM1 input), 40 MB
__device__ float g_h[(size_t)NN * 400];    // post-GEMM1 pre-BN, 80 MB
__device__ float g_h1[(size_t)NN * 200];   // layer-1 output, 40 MB
__device__ float g_bnsum[400];
__device__ float g_bnsq[400];
__device__ float g_scale[400];
__device__ float g_shift[400];

// ---------------- CSR build ----------------
__global__ void k_init_deg() {
    int i = blockIdx.x * blockDim.x + threadIdx.x;
    if (i < NN) g_deg[i] = 0;
}

__global__ void k_count(const int* __restrict__ dst) {
    int e = blockIdx.x * blockDim.x + threadIdx.x;
    if (e < NE) atomicAdd(&g_deg[dst[e]], 1);
}

__global__ void k_scan_local() {
    __shared__ int sm[512];
    int tid = threadIdx.x;
    int i = blockIdx.x * 512 + tid;
    int v = (i < NN) ? g_deg[i] : 0;
    sm[tid] = v;
    __syncthreads();
    for (int off = 1; off < 512; off <<= 1) {
        int t = (tid >= off) ? sm[tid - off] : 0;
        __syncthreads();
        sm[tid] += t;
        __syncthreads();
    }
    if (i < NN) g_rowstart[i] = sm[tid] - v;  // exclusive within block
    if (tid == 511) g_blocksum[blockIdx.x] = sm[511];
}

__global__ void k_scan_top(int nb) {
    __shared__ int sm[128];
    int tid = threadIdx.x;
    int v = (tid < nb) ? g_blocksum[tid] : 0;
    sm[tid] = v;
    __syncthreads();
    for (int off = 1; off < 128; off <<= 1) {
        int t = (tid >= off) ? sm[tid - off] : 0;
        __syncthreads();
        sm[tid] += t;
        __syncthreads();
    }
    if (tid < nb) g_blockoff[tid] = sm[tid] - v;  // exclusive
}

__global__ void k_scan_add() {
    int i = blockIdx.x * blockDim.x + threadIdx.x;
    if (i < NN) {
        int r = g_rowstart[i] + g_blockoff[i >> 9];
        g_rowstart[i] = r;
        g_cursor[i] = r;
    }
}

__global__ void k_fill(const int* __restrict__ src, const int* __restrict__ dst) {
    int e = blockIdx.x * blockDim.x + threadIdx.x;
    if (e < NE) {
        int d = dst[e];
        int pos = atomicAdd(&g_cursor[d], 1);
        g_srcs[pos] = src[e];
    }
}

// ---------------- aggregation: warp-per-node online softmax ----------------
template <int D>
__global__ void k_aggregate(const float* __restrict__ x, float* __restrict__ out) {
    constexpr int C = (D + 31) / 32;
    int warp = threadIdx.x >> 5;
    int node = blockIdx.x * (blockDim.x >> 5) + warp;
    if (node >= NN) return;
    int lane = threadIdx.x & 31;

    float m[C], S[C], W[C];
#pragma unroll
    for (int c = 0; c < C; c++) { m[c] = -1e30f; S[c] = 0.f; W[c] = 0.f; }

    int rs = g_rowstart[node];
    int deg = g_deg[node];

    int s_next = (deg > 0) ? g_srcs[rs] : 0;
    for (int j = 0; j < deg; j++) {
        int s = s_next;
        if (j + 1 < deg) s_next = g_srcs[rs + j + 1];
        const float* __restrict__ xr = x + (size_t)s * D;
#pragma unroll
        for (int c = 0; c < C; c++) {
            int ch = lane + 32 * c;
            if ((D % 32 == 0) || ch < D) {
                float v = fmaxf(xr[ch], 0.f) + MSG_EPS;
                if (v > m[c]) {
                    float sc = __expf(m[c] - v);
                    S[c] = S[c] * sc + 1.f;
                    W[c] = W[c] * sc + v;
                    m[c] = v;
                } else {
                    float e = __expf(v - m[c]);
                    S[c] += e;
                    W[c] += v * e;
                }
            }
        }
    }

    const float* __restrict__ xr = x + (size_t)node * D;
    float* __restrict__ orow = out + (size_t)node * D;
#pragma unroll
    for (int c = 0; c < C; c++) {
        int ch = lane + 32 * c;
        if ((D % 32 == 0) || ch < D) {
            float agg = (deg > 0) ? (W[c] / (S[c] + 1e-16f)) : 0.f;
            orow[ch] = agg + xr[ch];
        }
    }
}

// ---------------- tiled SGEMM ----------------
#define BM 128
#define BN 64
#define BK 8
#define TM 8
#define TN 4

template <bool TA, bool STATS, bool RELU>
__global__ void __launch_bounds__(256) k_gemm(
    const float* __restrict__ A, const float* __restrict__ B,
    const float* __restrict__ bias, float* __restrict__ C,
    int M, int K, int Nc) {
    __shared__ float As[BK][BM + 4];
    __shared__ float Bs[BK][BN];
    __shared__ float sp[16][BN];

    int tid = threadIdx.x;
    int tx = tid & 15;
    int ty = tid >> 4;
    int m0 = blockIdx.y * BM;
    int n0 = blockIdx.x * BN;

    float acc[TM][TN];
#pragma unroll
    for (int i = 0; i < TM; i++)
#pragma unroll
        for (int j = 0; j < TN; j++) acc[i][j] = 0.f;

    int ar = tid >> 1;
    int ak = (tid & 1) * 4;
    int bk = tid >> 4;
    int bc = (tid & 15) * 4;

    for (int k0 = 0; k0 < K; k0 += BK) {
        float4 av = make_float4(0.f, 0.f, 0.f, 0.f);
        int gm = m0 + ar;
        if (gm < M) av = *(const float4*)(A + (size_t)gm * K + k0 + ak);
        if (TA) {
            av.x = fmaxf(av.x * g_scale[k0 + ak + 0] + g_shift[k0 + ak + 0], 0.f);
            av.y = fmaxf(av.y * g_scale[k0 + ak + 1] + g_shift[k0 + ak + 1], 0.f);
            av.z = fmaxf(av.z * g_scale[k0 + ak + 2] + g_shift[k0 + ak + 2], 0.f);
            av.w = fmaxf(av.w * g_scale[k0 + ak + 3] + g_shift[k0 + ak + 3], 0.f);
        }
        As[ak + 0][ar] = av.x;
        As[ak + 1][ar] = av.y;
        As[ak + 2][ar] = av.z;
        As[ak + 3][ar] = av.w;

        if (tid < 128) {
            float4 bv = make_float4(0.f, 0.f, 0.f, 0.f);
            int gn = n0 + bc;
            if (gn < Nc) bv = *(const float4*)(B + (size_t)(k0 + bk) * Nc + gn);
            Bs[bk][bc + 0] = bv.x;
            Bs[bk][bc + 1] = bv.y;
            Bs[bk][bc + 2] = bv.z;
            Bs[bk][bc + 3] = bv.w;
        }
        __syncthreads();

#pragma unroll
        for (int kk = 0; kk < BK; kk++) {
            float4 ra0 = *(const float4*)&As[kk][ty * TM];
            float4 ra1 = *(const float4*)&As[kk][ty * TM + 4];
            float4 rb = *(const float4*)&Bs[kk][tx * TN];
            float ra[TM] = {ra0.x, ra0.y, ra0.z, ra0.w, ra1.x, ra1.y, ra1.z, ra1.w};
            float rbv[TN] = {rb.x, rb.y, rb.z, rb.w};
#pragma unroll
            for (int i = 0; i < TM; i++)
#pragma unroll
                for (int j = 0; j < TN; j++) acc[i][j] += ra[i] * rbv[j];
        }
        __syncthreads();
    }

    float bj[TN];
#pragma unroll
    for (int j = 0; j < TN; j++) {
        int cn = n0 + tx * TN + j;
        bj[j] = (cn < Nc) ? bias[cn] : 0.f;
    }
    float colsum[TN], colsq[TN];
#pragma unroll
    for (int j = 0; j < TN; j++) { colsum[j] = 0.f; colsq[j] = 0.f; }

#pragma unroll
    for (int i = 0; i < TM; i++) {
        int gm = m0 + ty * TM + i;
        if (gm < M) {
#pragma unroll
            for (int j = 0; j < TN; j++) {
                int cn = n0 + tx * TN + j;
                if (cn < Nc) {
                    float v = acc[i][j] + bj[j];
                    if (RELU) v = fmaxf(v, 0.f);
                    C[(size_t)gm * Nc + cn] = v;
                    if (STATS) { colsum[j] += v; colsq[j] += v * v; }
                }
            }
        }
    }

    if (STATS) {
#pragma unroll
        for (int j = 0; j < TN; j++) sp[ty][tx * TN + j] = colsum[j];
        __syncthreads();
        if (tid < BN) {
            float t = 0.f;
#pragma unroll
            for (int y = 0; y < 16; y++) t += sp[y][tid];
            if (n0 + tid < Nc) atomicAdd(&g_bnsum[n0 + tid], t);
        }
        __syncthreads();
#pragma unroll
        for (int j = 0; j < TN; j++) sp[ty][tx * TN + j] = colsq[j];
        __syncthreads();
        if (tid < BN) {
            float t = 0.f;
#pragma unroll
            for (int y = 0; y < 16; y++) t += sp[y][tid];
            if (n0 + tid < Nc) atomicAdd(&g_bnsq[n0 + tid], t);
        }
    }
}

// ---------------- BN helpers ----------------
__global__ void k_zero_bn() {
    int i = threadIdx.x;
    if (i < 400) { g_bnsum[i] = 0.f; g_bnsq[i] = 0.f; }
}

__global__ void k_bn_finalize(const float* __restrict__ g, const float* __restrict__ be, int mid) {
    int c = threadIdx.x;
    if (c < mid) {
        float mu = g_bnsum[c] * (1.f / NN);
        float var = g_bnsq[c] * (1.f / NN) - mu * mu;
        float sc = g[c] * rsqrtf(var + BN_EPS);
        g_scale[c] = sc;
        g_shift[c] = be[c] - mu * sc;
    }
}

// ---------------- final projection: [N,400] -> [N,2], warp per row ----------------
__global__ void k_out(const float* __restrict__ h, const float* __restrict__ w2,
                      const float* __restrict__ b2, float* __restrict__ out) {
    int warp = threadIdx.x >> 5;
    int row = blockIdx.x * 8 + warp;
    if (row >= NN) return;
    int lane = threadIdx.x & 31;
    const float* __restrict__ hr = h + (size_t)row * MID2;
    float a0 = 0.f, a1 = 0.f;
#pragma unroll
    for (int k = lane; k < MID2; k += 32) {
        float a = fmaxf(hr[k] * g_scale[k] + g_shift[k], 0.f);
        a0 += a * w2[2 * k];
        a1 += a * w2[2 * k + 1];
    }
#pragma unroll
    for (int off = 16; off; off >>= 1) {
        a0 += __shfl_xor_sync(0xffffffff, a0, off);
        a1 += __shfl_xor_sync(0xffffffff, a1, off);
    }
    if (lane == 0) {
        out[2 * row + 0] = fmaxf(a0 + b2[0], 0.f);
        out[2 * row + 1] = fmaxf(a1 + b2[1], 0.f);
    }
}

// ---------------- launcher ----------------
extern "C" void kernel_launch(void* const* d_in, const int* in_sizes, int n_in,
                              void* d_out, int out_size) {
    (void)out_size;
    // --- size-based input resolution (robust to metadata ordering) ---
    int ix = -1, iei = -1, ic1w1 = -1, ic1w2 = -1, ic2w1 = -1, ic2w2 = -1,
        ic2b2 = -1, ic1b2 = -1;
    int t256[3] = {-1, -1, -1}, n256 = 0;
    int t400[3] = {-1, -1, -1}, n400 = 0;
    for (int i = 0; i < n_in; i++) {
        switch (in_sizes[i]) {
            case NN * D1:       ix = i; break;       // 6,400,000
            case 2 * NE:        iei = i; break;      // 1,600,000
            case D1 * MID1:     ic1w1 = i; break;    // 32,768
            case MID1 * HIDC:   ic1w2 = i; break;    // 51,200
            case HIDC * MID2:   ic2w1 = i; break;    // 80,000
            case MID2 * OUTC:   ic2w2 = i; break;    // 800
            case OUTC:          ic2b2 = i; break;    // 2
            case HIDC:          ic1b2 = i; break;    // 200
            case MID1:          if (n256 < 3) t256[n256++] = i; break;
            case MID2:          if (n400 < 3) t400[n400++] = i; break;
        }
    }
    bool alpha = (iei > ic1w1);
    int ic1b1 = t256[0];
    int ic1g  = alpha ? t256[2] : t256[1];
    int ic1be = alpha ? t256[1] : t256[2];
    int ic2b1 = t400[0];
    int ic2g  = alpha ? t400[2] : t400[1];
    int ic2be = alpha ? t400[1] : t400[2];

    const float* x     = (const float*)d_in[ix];
    const int*   ei    = (const int*)d_in[iei];
    const int*   src   = ei;
    const int*   dst   = ei + NE;
    const float* c1_w1 = (const float*)d_in[ic1w1];
    const float* c1_b1 = (const float*)d_in[ic1b1];
    const float* c1_g  = (const float*)d_in[ic1g];
    const float* c1_be = (const float*)d_in[ic1be];
    const float* c1_w2 = (const float*)d_in[ic1w2];
    const float* c1_b2 = (const float*)d_in[ic1b2];
    const float* c2_w1 = (const float*)d_in[ic2w1];
    const float* c2_b1 = (const float*)d_in[ic2b1];
    const float* c2_g  = (const float*)d_in[ic2g];
    const float* c2_be = (const float*)d_in[ic2be];
    const float* c2_w2 = (const float*)d_in[ic2w2];
    const float* c2_b2 = (const float*)d_in[ic2b2];
    float* out = (float*)d_out;

    float *p_t, *p_h, *p_h1;
    cudaGetSymbolAddress((void**)&p_t, g_t);
    cudaGetSymbolAddress((void**)&p_h, g_h);
    cudaGetSymbolAddress((void**)&p_h1, g_h1);

    const int SCAN_BLOCKS = CEIL(NN, 512);  // 98

    // CSR build
    k_init_deg<<<CEIL(NN, 256), 256>>>();
    k_count<<<CEIL(NE, 256), 256>>>(dst);
    k_scan_local<<<SCAN_BLOCKS, 512>>>();
    k_scan_top<<<1, 128>>>(SCAN_BLOCKS);
    k_scan_add<<<CEIL(NN, 256), 256>>>();
    k_fill<<<CEIL(NE, 256), 256>>>(src, dst);

    // ---- layer 1 ----
    k_aggregate<D1><<<CEIL(NN, 8), 256>>>(x, p_t);
    k_zero_bn<<<1, 512>>>();
    k_gemm<false, true, false><<<dim3(CEIL(MID1, BN), CEIL(NN, BM)), 256>>>(
        p_t, c1_w1, c1_b1, p_h, NN, D1, MID1);
    k_bn_finalize<<<1, 512>>>(c1_g, c1_be, MID1);
    k_gemm<true, false, true><<<dim3(CEIL(HIDC, BN), CEIL(NN, BM)), 256>>>(
        p_h, c1_w2, c1_b2, p_h1, NN, MID1, HIDC);

    // ---- layer 2 ----
    k_aggregate<HIDC><<<CEIL(NN, 8), 256>>>(p_h1, p_t);
    k_zero_bn<<<1, 512>>>();
    k_gemm<false, true, false><<<dim3(CEIL(MID2, BN), CEIL(NN, BM)), 256>>>(
        p_t, c2_w1, c2_b1, p_h, NN, HIDC, MID2);   // <-- was MID2/BN = 6 (BUG), now 7
    k_bn_finalize<<<1, 512>>>(c2_g, c2_be, MID2);
    k_out<<<CEIL(NN, 8), 256>>>(p_h, c2_w2, c2_b2, out);
}

// round 5
// speedup vs baseline: 1.2814x; 1.2814x over previous
#include <cuda_runtime.h>
#include <cuda_fp16.h>
#include <cstdint>

#define NN 50000
#define NE 800000
#define D1 128
#define MID1 256
#define HIDC 200
#define MID2 400
#define OUTC 2
#define MSG_EPS 1e-7f
#define BN_EPS 1e-5f
#define CEIL(a, b) (((a) + (b) - 1) / (b))

// ---------------- device scratch (static globals; no allocations) ----------------
__device__ int g_deg[NN];
__device__ int g_rowstart[NN];
__device__ int g_cursor[NN];
__device__ int g_srcs[NE];
__device__ int g_blocksum[128];
__device__ int g_blockoff[128];

__device__ float g_h[(size_t)NN * 400];    // GEMM fp32 outputs (pre-BN), 80 MB
__device__ float g_h1[(size_t)NN * 200];   // layer-1 output fp32, 40 MB
__device__ __half g_ah[(size_t)NN * 256];  // GEMM A hi (fp16), reused per GEMM
__device__ __half g_al[(size_t)NN * 256];  // GEMM A lo
__device__ __half g_bh[80000];             // GEMM B hi (weights)
__device__ __half g_bl[80000];             // GEMM B lo
__device__ float g_bnsum[400];
__device__ float g_bnsq[400];
__device__ float g_scale[400];
__device__ float g_shift[400];

__device__ __forceinline__ void split_f32(float v, __half& hi, __half& lo) {
    hi = __float2half(v);
    lo = __float2half(v - __half2float(hi));
}

// ---------------- CSR build ----------------
__global__ void k_init_deg() {
    int i = blockIdx.x * blockDim.x + threadIdx.x;
    if (i < NN) g_deg[i] = 0;
}

__global__ void k_count(const int* __restrict__ dst) {
    int e = blockIdx.x * blockDim.x + threadIdx.x;
    if (e < NE) atomicAdd(&g_deg[dst[e]], 1);
}

__global__ void k_scan_local() {
    __shared__ int sm[512];
    int tid = threadIdx.x;
    int i = blockIdx.x * 512 + tid;
    int v = (i < NN) ? g_deg[i] : 0;
    sm[tid] = v;
    __syncthreads();
    for (int off = 1; off < 512; off <<= 1) {
        int t = (tid >= off) ? sm[tid - off] : 0;
        __syncthreads();
        sm[tid] += t;
        __syncthreads();
    }
    if (i < NN) g_rowstart[i] = sm[tid] - v;
    if (tid == 511) g_blocksum[blockIdx.x] = sm[511];
}

__global__ void k_scan_top(int nb) {
    __shared__ int sm[128];
    int tid = threadIdx.x;
    int v = (tid < nb) ? g_blocksum[tid] : 0;
    sm[tid] = v;
    __syncthreads();
    for (int off = 1; off < 128; off <<= 1) {
        int t = (tid >= off) ? sm[tid - off] : 0;
        __syncthreads();
        sm[tid] += t;
        __syncthreads();
    }
    if (tid < nb) g_blockoff[tid] = sm[tid] - v;
}

__global__ void k_scan_add() {
    int i = blockIdx.x * blockDim.x + threadIdx.x;
    if (i < NN) {
        int r = g_rowstart[i] + g_blockoff[i >> 9];
        g_rowstart[i] = r;
        g_cursor[i] = r;
    }
}

__global__ void k_fill(const int* __restrict__ src, const int* __restrict__ dst) {
    int e = blockIdx.x * blockDim.x + threadIdx.x;
    if (e < NE) {
        int d = dst[e];
        int pos = atomicAdd(&g_cursor[d], 1);
        g_srcs[pos] = src[e];
    }
}

// ---------------- aggregation: warp-per-node online softmax; emits fp16 hi/lo ----------------
template <int D>
__global__ void k_aggregate(const float* __restrict__ x,
                            __half* __restrict__ oh, __half* __restrict__ ol) {
    constexpr int C = (D + 31) / 32;
    int warp = threadIdx.x >> 5;
    int node = blockIdx.x * (blockDim.x >> 5) + warp;
    if (node >= NN) return;
    int lane = threadIdx.x & 31;

    float m[C], S[C], W[C];
#pragma unroll
    for (int c = 0; c < C; c++) { m[c] = -1e30f; S[c] = 0.f; W[c] = 0.f; }

    int rs = g_rowstart[node];
    int deg = g_deg[node];

    int s_next = (deg > 0) ? g_srcs[rs] : 0;
    for (int j = 0; j < deg; j++) {
        int s = s_next;
        if (j + 1 < deg) s_next = g_srcs[rs + j + 1];
        const float* __restrict__ xr = x + (size_t)s * D;
#pragma unroll
        for (int c = 0; c < C; c++) {
            int ch = lane + 32 * c;
            if ((D % 32 == 0) || ch < D) {
                float v = fmaxf(xr[ch], 0.f) + MSG_EPS;
                if (v > m[c]) {
                    float sc = __expf(m[c] - v);
                    S[c] = S[c] * sc + 1.f;
                    W[c] = W[c] * sc + v;
                    m[c] = v;
                } else {
                    float e = __expf(v - m[c]);
                    S[c] += e;
                    W[c] += v * e;
                }
            }
        }
    }

    const float* __restrict__ xr = x + (size_t)node * D;
#pragma unroll
    for (int c = 0; c < C; c++) {
        int ch = lane + 32 * c;
        if ((D % 32 == 0) || ch < D) {
            float agg = (deg > 0) ? (W[c] / (S[c] + 1e-16f)) : 0.f;
            float val = agg + xr[ch];
            __half hh, hl;
            split_f32(val, hh, hl);
            oh[(size_t)node * D + ch] = hh;
            ol[(size_t)node * D + ch] = hl;
        }
    }
}

// ---------------- conversion kernels ----------------
__global__ void k_splitw(const float* __restrict__ w, __half* __restrict__ bh,
                         __half* __restrict__ bl, int n) {
    int i = blockIdx.x * blockDim.x + threadIdx.x;
    if (i < n) {
        __half hh, hl;
        split_f32(w[i], hh, hl);
        bh[i] = hh;
        bl[i] = hl;
    }
}

// BN-normalize + ReLU + fp16-split: A for GEMM1b (stride 256)
__global__ void k_bnsplit(const float* __restrict__ h, __half* __restrict__ ah,
                          __half* __restrict__ al) {
    int i = blockIdx.x * blockDim.x + threadIdx.x;
    if (i < NN * MID1) {
        int c = i & (MID1 - 1);
        float v = fmaxf(h[i] * g_scale[c] + g_shift[c], 0.f);
        __half hh, hl;
        split_f32(v, hh, hl);
        ah[i] = hh;
        al[i] = hl;
    }
}

// ---------------- tensor-core GEMM: fp16 hi/lo split, 3-MMA, fp32 accum ----------------
#define MMA16816(d0, d1, d2, d3, a0, a1, a2, a3, b0, b1)                              \
    asm volatile(                                                                     \
        "mma.sync.aligned.m16n8k16.row.col.f32.f16.f16.f32 "                          \
        "{%0,%1,%2,%3}, {%4,%5,%6,%7}, {%8,%9}, {%0,%1,%2,%3};"                       \
        : "+f"(d0), "+f"(d1), "+f"(d2), "+f"(d3)                                      \
        : "r"(a0), "r"(a1), "r"(a2), "r"(a3), "r"(b0), "r"(b1))

template <bool STATS, bool RELU>
__global__ void __launch_bounds__(256) k_hgemm(
    const __half* __restrict__ Ah, const __half* __restrict__ Al,
    const __half* __restrict__ Bh, const __half* __restrict__ Bl,
    const float* __restrict__ bias, float* __restrict__ C,
    int M, int K, int N) {
    __shared__ __half sAh[128][40];
    __shared__ __half sAl[128][40];
    __shared__ __half sBh[32][72];
    __shared__ __half sBl[32][72];
    __shared__ float spsum[8][32];
    __shared__ float spsq[8][32];

    int tid = threadIdx.x;
    int w = tid >> 5, lane = tid & 31;
    int wy = w >> 1, wx = w & 1;
    int g = lane >> 2, t = lane & 3;
    int m0 = blockIdx.y * 128, n0 = blockIdx.x * 64;

    float acc[2][4][4];
#pragma unroll
    for (int mi = 0; mi < 2; mi++)
#pragma unroll
        for (int ni = 0; ni < 4; ni++)
#pragma unroll
            for (int c = 0; c < 4; c++) acc[mi][ni][c] = 0.f;

    for (int k0 = 0; k0 < K; k0 += 32) {
        // A tiles: 128x32 halfs x2; 512 8-half vectors per tile, 2 per thread
#pragma unroll
        for (int i = 0; i < 2; i++) {
            int v = tid * 2 + i;
            int r = v >> 2, kk = (v & 3) * 8;
            int gm = m0 + r, gk = k0 + kk;
            uint4 vh = make_uint4(0, 0, 0, 0), vl = make_uint4(0, 0, 0, 0);
            if (gm < M && gk < K) {  // K % 8 == 0 -> vector fully in-range
                vh = *(const uint4*)(Ah + (size_t)gm * K + gk);
                vl = *(const uint4*)(Al + (size_t)gm * K + gk);
            }
            *(uint4*)&sAh[r][kk] = vh;
            *(uint4*)&sAl[r][kk] = vl;
        }
        // B tiles: 32x64 halfs x2; 256 vectors, 1 per thread
        {
            int kk = tid >> 3;
            int nn = (tid & 7) * 8;
            int gk = k0 + kk, gn = n0 + nn;
            uint4 vh = make_uint4(0, 0, 0, 0), vl = make_uint4(0, 0, 0, 0);
            if (gk < K && gn < N) {  // N % 8 == 0
                vh = *(const uint4*)(Bh + (size_t)gk * N + gn);
                vl = *(const uint4*)(Bl + (size_t)gk * N + gn);
            }
            *(uint4*)&sBh[kk][nn] = vh;
            *(uint4*)&sBl[kk][nn] = vl;
        }
        __syncthreads();

#pragma unroll
        for (int kc = 0; kc < 2; kc++) {
            int kb = kc * 16;
            uint32_t fah[2][4], fal[2][4];
#pragma unroll
            for (int mi = 0; mi < 2; mi++) {
                int row = wy * 32 + mi * 16;
                fah[mi][0] = *(const uint32_t*)&sAh[row + g][kb + 2 * t];
                fah[mi][1] = *(const uint32_t*)&sAh[row + g + 8][kb + 2 * t];
                fah[mi][2] = *(const uint32_t*)&sAh[row + g][kb + 2 * t + 8];
                fah[mi][3] = *(const uint32_t*)&sAh[row + g + 8][kb + 2 * t + 8];
                fal[mi][0] = *(const uint32_t*)&sAl[row + g][kb + 2 * t];
                fal[mi][1] = *(const uint32_t*)&sAl[row + g + 8][kb + 2 * t];
                fal[mi][2] = *(const uint32_t*)&sAl[row + g][kb + 2 * t + 8];
                fal[mi][3] = *(const uint32_t*)&sAl[row + g + 8][kb + 2 * t + 8];
            }
            uint32_t fbh[4][2], fbl[4][2];
#pragma unroll
            for (int ni = 0; ni < 4; ni++) {
                int col = wx * 32 + ni * 8 + g;
                __half2 h0 = __halves2half2(sBh[kb + 2 * t][col], sBh[kb + 2 * t + 1][col]);
                __half2 h1 = __halves2half2(sBh[kb + 2 * t + 8][col], sBh[kb + 2 * t + 9][col]);
                fbh[ni][0] = *(uint32_t*)&h0;
                fbh[ni][1] = *(uint32_t*)&h1;
                __half2 l0 = __halves2half2(sBl[kb + 2 * t][col], sBl[kb + 2 * t + 1][col]);
                __half2 l1 = __halves2half2(sBl[kb + 2 * t + 8][col], sBl[kb + 2 * t + 9][col]);
                fbl[ni][0] = *(uint32_t*)&l0;
                fbl[ni][1] = *(uint32_t*)&l1;
            }
#pragma unroll
            for (int mi = 0; mi < 2; mi++)
#pragma unroll
                for (int ni = 0; ni < 4; ni++) {
                    MMA16816(acc[mi][ni][0], acc[mi][ni][1], acc[mi][ni][2], acc[mi][ni][3],
                             fah[mi][0], fah[mi][1], fah[mi][2], fah[mi][3],
                             fbh[ni][0], fbh[ni][1]);
                    MMA16816(acc[mi][ni][0], acc[mi][ni][1], acc[mi][ni][2], acc[mi][ni][3],
                             fal[mi][0], fal[mi][1], fal[mi][2], fal[mi][3],
                             fbh[ni][0], fbh[ni][1]);
                    MMA16816(acc[mi][ni][0], acc[mi][ni][1], acc[mi][ni][2], acc[mi][ni][3],
                             fah[mi][0], fah[mi][1], fah[mi][2], fah[mi][3],
                             fbl[ni][0], fbl[ni][1]);
                }
        }
        __syncthreads();
    }

    // ---- epilogue ----
    float bj[4][2];
#pragma unroll
    for (int ni = 0; ni < 4; ni++) {
        int cn = n0 + wx * 32 + ni * 8 + 2 * t;
        bj[ni][0] = (cn < N) ? bias[cn] : 0.f;
        bj[ni][1] = (cn + 1 < N) ? bias[cn + 1] : 0.f;
    }
    float colsum[4][2], colsq[4][2];
#pragma unroll
    for (int ni = 0; ni < 4; ni++) {
        colsum[ni][0] = colsum[ni][1] = 0.f;
        colsq[ni][0] = colsq[ni][1] = 0.f;
    }

#pragma unroll
    for (int mi = 0; mi < 2; mi++)
#pragma unroll
        for (int r8 = 0; r8 < 2; r8++) {
            int gm = m0 + wy * 32 + mi * 16 + g + r8 * 8;
            bool rowok = gm < M;
#pragma unroll
            for (int ni = 0; ni < 4; ni++) {
                int cn = n0 + wx * 32 + ni * 8 + 2 * t;
                float v0 = acc[mi][ni][r8 * 2 + 0] + bj[ni][0];
                float v1 = acc[mi][ni][r8 * 2 + 1] + bj[ni][1];
                if (RELU) { v0 = fmaxf(v0, 0.f); v1 = fmaxf(v1, 0.f); }
                if (rowok && cn < N)
                    *(float2*)(C + (size_t)gm * N + cn) = make_float2(v0, v1);
                if (STATS && rowok) {
                    colsum[ni][0] += v0;
                    colsum[ni][1] += v1;
                    colsq[ni][0] += v0 * v0;
                    colsq[ni][1] += v1 * v1;
                }
            }
        }

    if (STATS) {
#pragma unroll
        for (int ni = 0; ni < 4; ni++)
#pragma unroll
            for (int j = 0; j < 2; j++) {
                float s = colsum[ni][j], q = colsq[ni][j];
#pragma unroll
                for (int off = 4; off < 32; off <<= 1) {
                    s += __shfl_xor_sync(0xffffffff, s, off);
                    q += __shfl_xor_sync(0xffffffff, q, off);
                }
                if (lane < 4) {
                    spsum[w][ni * 8 + 2 * lane + j] = s;
                    spsq[w][ni * 8 + 2 * lane + j] = q;
                }
            }
        __syncthreads();
        if (tid < 64) {
            int wxsel = tid >> 5, local = tid & 31;
            float s = 0.f, q = 0.f;
#pragma unroll
            for (int yy = 0; yy < 4; yy++) {
                s += spsum[2 * yy + wxsel][local];
                q += spsq[2 * yy + wxsel][local];
            }
            int cn = n0 + wxsel * 32 + local;
            if (cn < N) {
                atomicAdd(&g_bnsum[cn], s);
                atomicAdd(&g_bnsq[cn], q);
            }
        }
    }
}

// ---------------- BN helpers ----------------
__global__ void k_zero_bn() {
    int i = threadIdx.x;
    if (i < 400) { g_bnsum[i] = 0.f; g_bnsq[i] = 0.f; }
}

__global__ void k_bn_finalize(const float* __restrict__ g, const float* __restrict__ be, int mid) {
    int c = threadIdx.x;
    if (c < mid) {
        float mu = g_bnsum[c] * (1.f / NN);
        float var = g_bnsq[c] * (1.f / NN) - mu * mu;
        float sc = g[c] * rsqrtf(var + BN_EPS);
        g_scale[c] = sc;
        g_shift[c] = be[c] - mu * sc;
    }
}

// ---------------- final projection: [N,400] -> [N,2], warp per row ----------------
__global__ void k_out(const float* __restrict__ h, const float* __restrict__ w2,
                      const float* __restrict__ b2, float* __restrict__ out) {
    int warp = threadIdx.x >> 5;
    int row = blockIdx.x * 8 + warp;
    if (row >= NN) return;
    int lane = threadIdx.x & 31;
    const float* __restrict__ hr = h + (size_t)row * MID2;
    float a0 = 0.f, a1 = 0.f;
#pragma unroll
    for (int k = lane; k < MID2; k += 32) {
        float a = fmaxf(hr[k] * g_scale[k] + g_shift[k], 0.f);
        a0 += a * w2[2 * k];
        a1 += a * w2[2 * k + 1];
    }
#pragma unroll
    for (int off = 16; off; off >>= 1) {
        a0 += __shfl_xor_sync(0xffffffff, a0, off);
        a1 += __shfl_xor_sync(0xffffffff, a1, off);
    }
    if (lane == 0) {
        out[2 * row + 0] = fmaxf(a0 + b2[0], 0.f);
        out[2 * row + 1] = fmaxf(a1 + b2[1], 0.f);
    }
}

// ---------------- launcher ----------------
extern "C" void kernel_launch(void* const* d_in, const int* in_sizes, int n_in,
                              void* d_out, int out_size) {
    (void)out_size;
    // --- size-based input resolution ---
    int ix = -1, iei = -1, ic1w1 = -1, ic1w2 = -1, ic2w1 = -1, ic2w2 = -1,
        ic2b2 = -1, ic1b2 = -1;
    int t256[3] = {-1, -1, -1}, n256 = 0;
    int t400[3] = {-1, -1, -1}, n400 = 0;
    for (int i = 0; i < n_in; i++) {
        switch (in_sizes[i]) {
            case NN * D1:     ix = i; break;
            case 2 * NE:      iei = i; break;
            case D1 * MID1:   ic1w1 = i; break;
            case MID1 * HIDC: ic1w2 = i; break;
            case HIDC * MID2: ic2w1 = i; break;
            case MID2 * OUTC: ic2w2 = i; break;
            case OUTC:        ic2b2 = i; break;
            case HIDC:        ic1b2 = i; break;
            case MID1:        if (n256 < 3) t256[n256++] = i; break;
            case MID2:        if (n400 < 3) t400[n400++] = i; break;
        }
    }
    bool alpha = (iei > ic1w1);
    int ic1b1 = t256[0];
    int ic1g  = alpha ? t256[2] : t256[1];
    int ic1be = alpha ? t256[1] : t256[2];
    int ic2b1 = t400[0];
    int ic2g  = alpha ? t400[2] : t400[1];
    int ic2be = alpha ? t400[1] : t400[2];

    const float* x     = (const float*)d_in[ix];
    const int*   ei    = (const int*)d_in[iei];
    const int*   src   = ei;
    const int*   dst   = ei + NE;
    const float* c1_w1 = (const float*)d_in[ic1w1];
    const float* c1_b1 = (const float*)d_in[ic1b1];
    const float* c1_g  = (const float*)d_in[ic1g];
    const float* c1_be = (const float*)d_in[ic1be];
    const float* c1_w2 = (const float*)d_in[ic1w2];
    const float* c1_b2 = (const float*)d_in[ic1b2];
    const float* c2_w1 = (const float*)d_in[ic2w1];
    const float* c2_b1 = (const float*)d_in[ic2b1];
    const float* c2_g  = (const float*)d_in[ic2g];
    const float* c2_be = (const float*)d_in[ic2be];
    const float* c2_w2 = (const float*)d_in[ic2w2];
    const float* c2_b2 = (const float*)d_in[ic2b2];
    float* out = (float*)d_out;

    float *p_h, *p_h1;
    __half *p_ah, *p_al, *p_bh, *p_bl;
    cudaGetSymbolAddress((void**)&p_h, g_h);
    cudaGetSymbolAddress((void**)&p_h1, g_h1);
    cudaGetSymbolAddress((void**)&p_ah, g_ah);
    cudaGetSymbolAddress((void**)&p_al, g_al);
    cudaGetSymbolAddress((void**)&p_bh, g_bh);
    cudaGetSymbolAddress((void**)&p_bl, g_bl);

    const int SCAN_BLOCKS = CEIL(NN, 512);
    const int MT = CEIL(NN, 128);  // 391 M-tiles

    // CSR build
    k_init_deg<<<CEIL(NN, 256), 256>>>();
    k_count<<<CEIL(NE, 256), 256>>>(dst);
    k_scan_local<<<SCAN_BLOCKS, 512>>>();
    k_scan_top<<<1, 128>>>(SCAN_BLOCKS);
    k_scan_add<<<CEIL(NN, 256), 256>>>();
    k_fill<<<CEIL(NE, 256), 256>>>(src, dst);

    // ---- layer 1 ----
    k_aggregate<D1><<<CEIL(NN, 8), 256>>>(x, p_ah, p_al);
    k_splitw<<<CEIL(D1 * MID1, 256), 256>>>(c1_w1, p_bh, p_bl, D1 * MID1);
    k_zero_bn<<<1, 512>>>();
    k_hgemm<true, false><<<dim3(CEIL(MID1, 64), MT), 256>>>(
        p_ah, p_al, p_bh, p_bl, c1_b1, p_h, NN, D1, MID1);
    k_bn_finalize<<<1, 512>>>(c1_g, c1_be, MID1);
    k_bnsplit<<<CEIL(NN * MID1, 256), 256>>>(p_h, p_ah, p_al);
    k_splitw<<<CEIL(MID1 * HIDC, 256), 256>>>(c1_w2, p_bh, p_bl, MID1 * HIDC);
    k_hgemm<false, true><<<dim3(CEIL(HIDC, 64), MT), 256>>>(
        p_ah, p_al, p_bh, p_bl, c1_b2, p_h1, NN, MID1, HIDC);

    // ---- layer 2 ----
    k_aggregate<HIDC><<<CEIL(NN, 8), 256>>>(p_h1, p_ah, p_al);
    k_splitw<<<CEIL(HIDC * MID2, 256), 256>>>(c2_w1, p_bh, p_bl, HIDC * MID2);
    k_zero_bn<<<1, 512>>>();
    k_hgemm<true, false><<<dim3(CEIL(MID2, 64), MT), 256>>>(
        p_ah, p_al, p_bh, p_bl, c2_b1, p_h, NN, HIDC, MID2);
    k_bn_finalize<<<1, 512>>>(c2_g, c2_be, MID2);
    k_out<<<CEIL(NN, 8), 256>>>(p_h, c2_w2, c2_b2, out);
}

// round 6
// speedup vs baseline: 1.7466x; 1.3631x over previous
#include <cuda_runtime.h>
#include <cuda_fp16.h>
#include <cstdint>

#define NN 50000
#define NE 800000
#define D1 128
#define MID1 256
#define HIDC 200
#define MID2 400
#define OUTC 2
#define MSG_EPS 1e-7f
#define BN_EPS 1e-5f
#define CEIL(a, b) (((a) + (b) - 1) / (b))

// ---------------- device scratch ----------------
__device__ int g_deg[NN];
__device__ int g_rowstart[NN];
__device__ int g_cursor[NN];
__device__ int g_srcs[NE];
__device__ int g_blocksum[128];
__device__ int g_blockoff[128];

__device__ float g_h[(size_t)NN * 400];
__device__ float g_h1[(size_t)NN * 200];
__device__ __half g_ah[(size_t)NN * 256];
__device__ __half g_al[(size_t)NN * 256];
__device__ __half g_bh[80000];
__device__ __half g_bl[80000];
__device__ float g_bnsum[400];
__device__ float g_bnsq[400];
__device__ float g_scale[400];
__device__ float g_shift[400];

__device__ __forceinline__ void split_f32(float v, __half& hi, __half& lo) {
    hi = __float2half(v);
    lo = __float2half(v - __half2float(hi));
}

// ---------------- CSR build ----------------
__global__ void k_init_deg() {
    int i = blockIdx.x * blockDim.x + threadIdx.x;
    if (i < NN) g_deg[i] = 0;
}

__global__ void k_count(const int* __restrict__ dst) {
    int e = blockIdx.x * blockDim.x + threadIdx.x;
    if (e < NE) atomicAdd(&g_deg[dst[e]], 1);
}

__global__ void k_scan_local() {
    __shared__ int sm[512];
    int tid = threadIdx.x;
    int i = blockIdx.x * 512 + tid;
    int v = (i < NN) ? g_deg[i] : 0;
    sm[tid] = v;
    __syncthreads();
    for (int off = 1; off < 512; off <<= 1) {
        int t = (tid >= off) ? sm[tid - off] : 0;
        __syncthreads();
        sm[tid] += t;
        __syncthreads();
    }
    if (i < NN) g_rowstart[i] = sm[tid] - v;
    if (tid == 511) g_blocksum[blockIdx.x] = sm[511];
}

__global__ void k_scan_top(int nb) {
    __shared__ int sm[128];
    int tid = threadIdx.x;
    int v = (tid < nb) ? g_blocksum[tid] : 0;
    sm[tid] = v;
    __syncthreads();
    for (int off = 1; off < 128; off <<= 1) {
        int t = (tid >= off) ? sm[tid - off] : 0;
        __syncthreads();
        sm[tid] += t;
        __syncthreads();
    }
    if (tid < nb) g_blockoff[tid] = sm[tid] - v;
}

__global__ void k_scan_add() {
    int i = blockIdx.x * blockDim.x + threadIdx.x;
    if (i < NN) {
        int r = g_rowstart[i] + g_blockoff[i >> 9];
        g_rowstart[i] = r;
        g_cursor[i] = r;
    }
}

__global__ void k_fill(const int* __restrict__ src, const int* __restrict__ dst) {
    int e = blockIdx.x * blockDim.x + threadIdx.x;
    if (e < NE) {
        int d = dst[e];
        int pos = atomicAdd(&g_cursor[d], 1);
        g_srcs[pos] = src[e];
    }
}

// ---------------- aggregation: warp-per-node, branch-free softmax, 2-edge unroll ----------------
// Direct exp(msg): msg ∈ [eps, ~7], exp ≤ ~1100, no overflow; identical ratio to
// the reference's max-subtracted softmax.
template <int D>
__global__ void k_aggregate(const float* __restrict__ x,
                            __half* __restrict__ oh, __half* __restrict__ ol) {
    constexpr int C = (D + 31) / 32;
    int warp = threadIdx.x >> 5;
    int node = blockIdx.x * (blockDim.x >> 5) + warp;
    if (node >= NN) return;
    int lane = threadIdx.x & 31;

    float S[C], W[C];
#pragma unroll
    for (int c = 0; c < C; c++) { S[c] = 0.f; W[c] = 0.f; }

    int rs = g_rowstart[node];
    int deg = g_deg[node];

    int j = 0;
    for (; j + 1 < deg; j += 2) {
        int sa = g_srcs[rs + j];
        int sb = g_srcs[rs + j + 1];
        const float* __restrict__ xra = x + (size_t)sa * D;
        const float* __restrict__ xrb = x + (size_t)sb * D;
        float va[C], vb[C];
#pragma unroll
        for (int c = 0; c < C; c++) {
            int ch = lane + 32 * c;
            if ((D % 32 == 0) || ch < D) {
                va[c] = __ldg(xra + ch);
                vb[c] = __ldg(xrb + ch);
            }
        }
#pragma unroll
        for (int c = 0; c < C; c++) {
            int ch = lane + 32 * c;
            if ((D % 32 == 0) || ch < D) {
                float a = fmaxf(va[c], 0.f) + MSG_EPS;
                float b = fmaxf(vb[c], 0.f) + MSG_EPS;
                float ea = __expf(a);
                float eb = __expf(b);
                S[c] += ea + eb;
                W[c] += a * ea + b * eb;
            }
        }
    }
    if (j < deg) {
        int sa = g_srcs[rs + j];
        const float* __restrict__ xra = x + (size_t)sa * D;
#pragma unroll
        for (int c = 0; c < C; c++) {
            int ch = lane + 32 * c;
            if ((D % 32 == 0) || ch < D) {
                float a = fmaxf(__ldg(xra + ch), 0.f) + MSG_EPS;
                float ea = __expf(a);
                S[c] += ea;
                W[c] += a * ea;
            }
        }
    }

    const float* __restrict__ xr = x + (size_t)node * D;
#pragma unroll
    for (int c = 0; c < C; c++) {
        int ch = lane + 32 * c;
        if ((D % 32 == 0) || ch < D) {
            float agg = (deg > 0) ? (W[c] / S[c]) : 0.f;
            float val = agg + xr[ch];
            __half hh, hl;
            split_f32(val, hh, hl);
            oh[(size_t)node * D + ch] = hh;
            ol[(size_t)node * D + ch] = hl;
        }
    }
}

// ---------------- conversion kernels ----------------
__global__ void k_splitw(const float* __restrict__ w, __half* __restrict__ bh,
                         __half* __restrict__ bl, int n) {
    int i = blockIdx.x * blockDim.x + threadIdx.x;
    if (i < n) {
        __half hh, hl;
        split_f32(w[i], hh, hl);
        bh[i] = hh;
        bl[i] = hl;
    }
}

__global__ void k_bnsplit(const float* __restrict__ h, __half* __restrict__ ah,
                          __half* __restrict__ al) {
    int i = blockIdx.x * blockDim.x + threadIdx.x;
    if (i < NN * MID1) {
        int c = i & (MID1 - 1);
        float v = fmaxf(h[i] * g_scale[c] + g_shift[c], 0.f);
        __half hh, hl;
        split_f32(v, hh, hl);
        ah[i] = hh;
        al[i] = hl;
    }
}

// ---------------- tensor-core GEMM: fp16 hi/lo split, ldmatrix fragments ----------------
#define MMA16816(d0, d1, d2, d3, a0, a1, a2, a3, b0, b1)                              \
    asm volatile(                                                                     \
        "mma.sync.aligned.m16n8k16.row.col.f32.f16.f16.f32 "                          \
        "{%0,%1,%2,%3}, {%4,%5,%6,%7}, {%8,%9}, {%0,%1,%2,%3};"                       \
        : "+f"(d0), "+f"(d1), "+f"(d2), "+f"(d3)                                      \
        : "r"(a0), "r"(a1), "r"(a2), "r"(a3), "r"(b0), "r"(b1))

#define LDSM4(r0, r1, r2, r3, addr)                                                  \
    asm volatile("ldmatrix.sync.aligned.m8n8.x4.shared.b16 {%0,%1,%2,%3}, [%4];"      \
                 : "=r"(r0), "=r"(r1), "=r"(r2), "=r"(r3) : "r"(addr))

#define LDSM2T(r0, r1, addr)                                                         \
    asm volatile("ldmatrix.sync.aligned.m8n8.x2.trans.shared.b16 {%0,%1}, [%2];"      \
                 : "=r"(r0), "=r"(r1) : "r"(addr))

template <bool STATS, bool RELU>
__global__ void __launch_bounds__(256) k_hgemm(
    const __half* __restrict__ Ah, const __half* __restrict__ Al,
    const __half* __restrict__ Bh, const __half* __restrict__ Bl,
    const float* __restrict__ bias, float* __restrict__ C,
    int M, int K, int N) {
    __shared__ __half sAh[128][40];
    __shared__ __half sAl[128][40];
    __shared__ __half sBh[32][72];
    __shared__ __half sBl[32][72];
    __shared__ float spsum[8][32];
    __shared__ float spsq[8][32];

    int tid = threadIdx.x;
    int w = tid >> 5, lane = tid & 31;
    int wy = w >> 1, wx = w & 1;
    int g = lane >> 2, t = lane & 3;
    int m0 = blockIdx.y * 128, n0 = blockIdx.x * 64;

    float acc[2][4][4];
#pragma unroll
    for (int mi = 0; mi < 2; mi++)
#pragma unroll
        for (int ni = 0; ni < 4; ni++)
#pragma unroll
            for (int c = 0; c < 4; c++) acc[mi][ni][c] = 0.f;

    // global-load staging registers (tile k+1 in flight during compute of k)
    uint4 rAh[2], rAl[2], rBh, rBl;
    int a_r = (tid * 2) >> 2;            // rows for this thread's two A vectors
    int a_r1 = (tid * 2 + 1) >> 2;
    int a_k0 = ((tid * 2) & 3) * 8;
    int a_k1 = ((tid * 2 + 1) & 3) * 8;
    int b_k = tid >> 3;
    int b_n = (tid & 7) * 8;

    auto gload = [&](int k0) {
        rAh[0] = make_uint4(0, 0, 0, 0); rAl[0] = make_uint4(0, 0, 0, 0);
        rAh[1] = make_uint4(0, 0, 0, 0); rAl[1] = make_uint4(0, 0, 0, 0);
        int gm0 = m0 + a_r, gk0 = k0 + a_k0;
        if (gm0 < M && gk0 < K) {
            rAh[0] = *(const uint4*)(Ah + (size_t)gm0 * K + gk0);
            rAl[0] = *(const uint4*)(Al + (size_t)gm0 * K + gk0);
        }
        int gm1 = m0 + a_r1, gk1 = k0 + a_k1;
        if (gm1 < M && gk1 < K) {
            rAh[1] = *(const uint4*)(Ah + (size_t)gm1 * K + gk1);
            rAl[1] = *(const uint4*)(Al + (size_t)gm1 * K + gk1);
        }
        rBh = make_uint4(0, 0, 0, 0); rBl = make_uint4(0, 0, 0, 0);
        int gk = k0 + b_k, gn = n0 + b_n;
        if (gk < K && gn < N) {
            rBh = *(const uint4*)(Bh + (size_t)gk * N + gn);
            rBl = *(const uint4*)(Bl + (size_t)gk * N + gn);
        }
    };
    auto sstore = [&]() {
        *(uint4*)&sAh[a_r][a_k0] = rAh[0];
        *(uint4*)&sAl[a_r][a_k0] = rAl[0];
        *(uint4*)&sAh[a_r1][a_k1] = rAh[1];
        *(uint4*)&sAl[a_r1][a_k1] = rAl[1];
        *(uint4*)&sBh[b_k][b_n] = rBh;
        *(uint4*)&sBl[b_k][b_n] = rBl;
    };

    int KT = CEIL(K, 32);
    gload(0);

    int lrow = lane & 15;
    int ksel = (lane >> 4) * 8;

    for (int kt = 0; kt < KT; kt++) {
        sstore();
        __syncthreads();
        if (kt + 1 < KT) gload((kt + 1) * 32);

#pragma unroll
        for (int kc = 0; kc < 2; kc++) {
            int kb = kc * 16;
            uint32_t fah[2][4], fal[2][4];
#pragma unroll
            for (int mi = 0; mi < 2; mi++) {
                int row = wy * 32 + mi * 16 + lrow;
                uint32_t ah_addr = (uint32_t)__cvta_generic_to_shared(&sAh[row][kb + ksel]);
                LDSM4(fah[mi][0], fah[mi][1], fah[mi][2], fah[mi][3], ah_addr);
                uint32_t al_addr = (uint32_t)__cvta_generic_to_shared(&sAl[row][kb + ksel]);
                LDSM4(fal[mi][0], fal[mi][1], fal[mi][2], fal[mi][3], al_addr);
            }
            uint32_t fbh[4][2], fbl[4][2];
            int krow = kb + (lane & 15);
#pragma unroll
            for (int ni = 0; ni < 4; ni++) {
                int col = wx * 32 + ni * 8;
                uint32_t bh_addr = (uint32_t)__cvta_generic_to_shared(&sBh[krow][col]);
                LDSM2T(fbh[ni][0], fbh[ni][1], bh_addr);
                uint32_t bl_addr = (uint32_t)__cvta_generic_to_shared(&sBl[krow][col]);
                LDSM2T(fbl[ni][0], fbl[ni][1], bl_addr);
            }
#pragma unroll
            for (int mi = 0; mi < 2; mi++)
#pragma unroll
                for (int ni = 0; ni < 4; ni++) {
                    MMA16816(acc[mi][ni][0], acc[mi][ni][1], acc[mi][ni][2], acc[mi][ni][3],
                             fah[mi][0], fah[mi][1], fah[mi][2], fah[mi][3],
                             fbh[ni][0], fbh[ni][1]);
                    MMA16816(acc[mi][ni][0], acc[mi][ni][1], acc[mi][ni][2], acc[mi][ni][3],
                             fal[mi][0], fal[mi][1], fal[mi][2], fal[mi][3],
                             fbh[ni][0], fbh[ni][1]);
                    MMA16816(acc[mi][ni][0], acc[mi][ni][1], acc[mi][ni][2], acc[mi][ni][3],
                             fah[mi][0], fah[mi][1], fah[mi][2], fah[mi][3],
                             fbl[ni][0], fbl[ni][1]);
                }
        }
        __syncthreads();
    }

    // ---- epilogue ----
    float bj[4][2];
#pragma unroll
    for (int ni = 0; ni < 4; ni++) {
        int cn = n0 + wx * 32 + ni * 8 + 2 * t;
        bj[ni][0] = (cn < N) ? bias[cn] : 0.f;
        bj[ni][1] = (cn + 1 < N) ? bias[cn + 1] : 0.f;
    }
    float colsum[4][2], colsq[4][2];
#pragma unroll
    for (int ni = 0; ni < 4; ni++) {
        colsum[ni][0] = colsum[ni][1] = 0.f;
        colsq[ni][0] = colsq[ni][1] = 0.f;
    }

#pragma unroll
    for (int mi = 0; mi < 2; mi++)
#pragma unroll
        for (int r8 = 0; r8 < 2; r8++) {
            int gm = m0 + wy * 32 + mi * 16 + g + r8 * 8;
            bool rowok = gm < M;
#pragma unroll
            for (int ni = 0; ni < 4; ni++) {
                int cn = n0 + wx * 32 + ni * 8 + 2 * t;
                float v0 = acc[mi][ni][r8 * 2 + 0] + bj[ni][0];
                float v1 = acc[mi][ni][r8 * 2 + 1] + bj[ni][1];
                if (RELU) { v0 = fmaxf(v0, 0.f); v1 = fmaxf(v1, 0.f); }
                if (rowok && cn < N)
                    *(float2*)(C + (size_t)gm * N + cn) = make_float2(v0, v1);
                if (STATS && rowok) {
                    colsum[ni][0] += v0;
                    colsum[ni][1] += v1;
                    colsq[ni][0] += v0 * v0;
                    colsq[ni][1] += v1 * v1;
                }
            }
        }

    if (STATS) {
#pragma unroll
        for (int ni = 0; ni < 4; ni++)
#pragma unroll
            for (int j = 0; j < 2; j++) {
                float s = colsum[ni][j], q = colsq[ni][j];
#pragma unroll
                for (int off = 4; off < 32; off <<= 1) {
                    s += __shfl_xor_sync(0xffffffff, s, off);
                    q += __shfl_xor_sync(0xffffffff, q, off);
                }
                if (lane < 4) {
                    spsum[w][ni * 8 + 2 * lane + j] = s;
                    spsq[w][ni * 8 + 2 * lane + j] = q;
                }
            }
        __syncthreads();
        if (tid < 64) {
            int wxsel = tid >> 5, local = tid & 31;
            float s = 0.f, q = 0.f;
#pragma unroll
            for (int yy = 0; yy < 4; yy++) {
                s += spsum[2 * yy + wxsel][local];
                q += spsq[2 * yy + wxsel][local];
            }
            int cn = n0 + wxsel * 32 + local;
            if (cn < N) {
                atomicAdd(&g_bnsum[cn], s);
                atomicAdd(&g_bnsq[cn], q);
            }
        }
    }
}

// ---------------- BN helpers ----------------
__global__ void k_zero_bn() {
    int i = threadIdx.x;
    if (i < 400) { g_bnsum[i] = 0.f; g_bnsq[i] = 0.f; }
}

__global__ void k_bn_finalize(const float* __restrict__ g, const float* __restrict__ be, int mid) {
    int c = threadIdx.x;
    if (c < mid) {
        float mu = g_bnsum[c] * (1.f / NN);
        float var = g_bnsq[c] * (1.f / NN) - mu * mu;
        float sc = g[c] * rsqrtf(var + BN_EPS);
        g_scale[c] = sc;
        g_shift[c] = be[c] - mu * sc;
    }
}

// ---------------- final projection ----------------
__global__ void k_out(const float* __restrict__ h, const float* __restrict__ w2,
                      const float* __restrict__ b2, float* __restrict__ out) {
    int warp = threadIdx.x >> 5;
    int row = blockIdx.x * 8 + warp;
    if (row >= NN) return;
    int lane = threadIdx.x & 31;
    const float* __restrict__ hr = h + (size_t)row * MID2;
    float a0 = 0.f, a1 = 0.f;
#pragma unroll
    for (int k = lane; k < MID2; k += 32) {
        float a = fmaxf(hr[k] * g_scale[k] + g_shift[k], 0.f);
        a0 += a * w2[2 * k];
        a1 += a * w2[2 * k + 1];
    }
#pragma unroll
    for (int off = 16; off; off >>= 1) {
        a0 += __shfl_xor_sync(0xffffffff, a0, off);
        a1 += __shfl_xor_sync(0xffffffff, a1, off);
    }
    if (lane == 0) {
        out[2 * row + 0] = fmaxf(a0 + b2[0], 0.f);
        out[2 * row + 1] = fmaxf(a1 + b2[1], 0.f);
    }
}

// ---------------- launcher ----------------
extern "C" void kernel_launch(void* const* d_in, const int* in_sizes, int n_in,
                              void* d_out, int out_size) {
    (void)out_size;
    int ix = -1, iei = -1, ic1w1 = -1, ic1w2 = -1, ic2w1 = -1, ic2w2 = -1,
        ic2b2 = -1, ic1b2 = -1;
    int t256[3] = {-1, -1, -1}, n256 = 0;
    int t400[3] = {-1, -1, -1}, n400 = 0;
    for (int i = 0; i < n_in; i++) {
        switch (in_sizes[i]) {
            case NN * D1:     ix = i; break;
            case 2 * NE:      iei = i; break;
            case D1 * MID1:   ic1w1 = i; break;
            case MID1 * HIDC: ic1w2 = i; break;
            case HIDC * MID2: ic2w1 = i; break;
            case MID2 * OUTC: ic2w2 = i; break;
            case OUTC:        ic2b2 = i; break;
            case HIDC:        ic1b2 = i; break;
            case MID1:        if (n256 < 3) t256[n256++] = i; break;
            case MID2:        if (n400 < 3) t400[n400++] = i; break;
        }
    }
    bool alpha = (iei > ic1w1);
    int ic1b1 = t256[0];
    int ic1g  = alpha ? t256[2] : t256[1];
    int ic1be = alpha ? t256[1] : t256[2];
    int ic2b1 = t400[0];
    int ic2g  = alpha ? t400[2] : t400[1];
    int ic2be = alpha ? t400[1] : t400[2];

    const float* x     = (const float*)d_in[ix];
    const int*   ei    = (const int*)d_in[iei];
    const int*   src   = ei;
    const int*   dst   = ei + NE;
    const float* c1_w1 = (const float*)d_in[ic1w1];
    const float* c1_b1 = (const float*)d_in[ic1b1];
    const float* c1_g  = (const float*)d_in[ic1g];
    const float* c1_be = (const float*)d_in[ic1be];
    const float* c1_w2 = (const float*)d_in[ic1w2];
    const float* c1_b2 = (const float*)d_in[ic1b2];
    const float* c2_w1 = (const float*)d_in[ic2w1];
    const float* c2_b1 = (const float*)d_in[ic2b1];
    const float* c2_g  = (const float*)d_in[ic2g];
    const float* c2_be = (const float*)d_in[ic2be];
    const float* c2_w2 = (const float*)d_in[ic2w2];
    const float* c2_b2 = (const float*)d_in[ic2b2];
    float* out = (float*)d_out;

    float *p_h, *p_h1;
    __half *p_ah, *p_al, *p_bh, *p_bl;
    cudaGetSymbolAddress((void**)&p_h, g_h);
    cudaGetSymbolAddress((void**)&p_h1, g_h1);
    cudaGetSymbolAddress((void**)&p_ah, g_ah);
    cudaGetSymbolAddress((void**)&p_al, g_al);
    cudaGetSymbolAddress((void**)&p_bh, g_bh);
    cudaGetSymbolAddress((void**)&p_bl, g_bl);

    const int SCAN_BLOCKS = CEIL(NN, 512);
    const int MT = CEIL(NN, 128);

    // CSR build
    k_init_deg<<<CEIL(NN, 256), 256>>>();
    k_count<<<CEIL(NE, 256), 256>>>(dst);
    k_scan_local<<<SCAN_BLOCKS, 512>>>();
    k_scan_top<<<1, 128>>>(SCAN_BLOCKS);
    k_scan_add<<<CEIL(NN, 256), 256>>>();
    k_fill<<<CEIL(NE, 256), 256>>>(src, dst);

    // ---- layer 1 ----
    k_aggregate<D1><<<CEIL(NN, 8), 256>>>(x, p_ah, p_al);
    k_splitw<<<CEIL(D1 * MID1, 256), 256>>>(c1_w1, p_bh, p_bl, D1 * MID1);
    k_zero_bn<<<1, 512>>>();
    k_hgemm<true, false><<<dim3(CEIL(MID1, 64), MT), 256>>>(
        p_ah, p_al, p_bh, p_bl, c1_b1, p_h, NN, D1, MID1);
    k_bn_finalize<<<1, 512>>>(c1_g, c1_be, MID1);
    k_bnsplit<<<CEIL(NN * MID1, 256), 256>>>(p_h, p_ah, p_al);
    k_splitw<<<CEIL(MID1 * HIDC, 256), 256>>>(c1_w2, p_bh, p_bl, MID1 * HIDC);
    k_hgemm<false, true><<<dim3(CEIL(HIDC, 64), MT), 256>>>(
        p_ah, p_al, p_bh, p_bl, c1_b2, p_h1, NN, MID1, HIDC);

    // ---- layer 2 ----
    k_aggregate<HIDC><<<CEIL(NN, 8), 256>>>(p_h1, p_ah, p_al);
    k_splitw<<<CEIL(HIDC * MID2, 256), 256>>>(c2_w1, p_bh, p_bl, HIDC * MID2);
    k_zero_bn<<<1, 512>>>();
    k_hgemm<true, false><<<dim3(CEIL(MID2, 64), MT), 256>>>(
        p_ah, p_al, p_bh, p_bl, c2_b1, p_h, NN, HIDC, MID2);
    k_bn_finalize<<<1, 512>>>(c2_g, c2_be, MID2);
    k_out<<<CEIL(NN, 8), 256>>>(p_h, c2_w2, c2_b2, out);
}